// round 11
// baseline (speedup 1.0000x reference)
#include <cuda_runtime.h>
#include <math.h>
#include <stdint.h>

#define BATCH   65536
#define IN_DIM  512
#define LATENT  32
#define NTRI    528
#define NPAD    544            // W_ch padded row (floats)
#define WENC_PAD 524           // conflict-free float4 weight rows
#define THREADS 512
#define WARPS   16
#define RPW     8              // rows per warp-tile (enc)
#define TILE_ROWS (WARPS*RPW)  // 128
#define NTILES  (BATCH/TILE_ROWS) // 512
#define GRID    152

#define XQ      136            // per-row stride (floats) of quarter-K x stage (128 + 8 pad)
#define LOFF_B  560            // cov buffer-B offset (bank set differs by 16 from A)
#define WBUF_FLOATS 1088       // per-warp buffer: 8x136 x-quarters OR two packed-tri L rows

// ---- smem layout (floats) ----
#define OFF_WENC 0
#define SZ_WENC  (LATENT*WENC_PAD)              // 16768
#define OFF_WCH  (OFF_WENC + SZ_WENC)           // 16768
#define SZ_WCH   (LATENT*NPAD)                  // 17408
#define OFF_WMU  (OFF_WCH + SZ_WCH)             // 34176
#define OFF_BENC (OFF_WMU + LATENT*LATENT)      // 35200
#define OFF_BMU  (OFF_BENC + 32)                // 35232
#define OFF_BCH  (OFF_BMU + 32)                 // 35264 (544)
#define OFF_S    (OFF_BCH + NPAD)               // 35808
#define OFF_WBUF (OFF_S + 32)                   // 35840 (16B aligned)
#define SMEM_FLOATS (OFF_WBUF + WARPS*WBUF_FLOATS) // 53248 floats = 212992 B

#define MU_OFF  ((size_t)BATCH*LATENT)
#define COV_OFF ((size_t)BATCH*LATENT*2)

__device__ __forceinline__ float lrelu(float v) { return v >= 0.f ? v : 0.01f * v; }

__global__ void __launch_bounds__(THREADS)
pm_kernel(const float* __restrict__ x,       const float* __restrict__ W_enc,
          const float* __restrict__ b_enc,   const float* __restrict__ bn_gamma,
          const float* __restrict__ bn_beta, const float* __restrict__ bn_mean,
          const float* __restrict__ bn_var,  const float* __restrict__ W_mu,
          const float* __restrict__ b_mu,    const float* __restrict__ W_ch,
          const float* __restrict__ b_ch,    float* __restrict__ out)
{
    extern __shared__ float sm[];
    const int tid = threadIdx.x;

    // ---- stage + fold weights into smem ----
    if (tid < 32) {
        float s = bn_gamma[tid] * rsqrtf(bn_var[tid] + 1e-5f);
        sm[OFF_S + tid]    = s;
        sm[OFF_BENC + tid] = (b_enc[tid] - bn_mean[tid]) * s + bn_beta[tid];
        sm[OFF_BMU + tid]  = b_mu[tid];
    }
    __syncthreads();
    for (int idx = tid; idx < IN_DIM * LATENT; idx += THREADS) {
        int k = idx >> 5, j = idx & 31;
        sm[OFF_WENC + j * WENC_PAD + k] = W_enc[idx] * sm[OFF_S + j];  // transposed + BN fold
    }
    for (int idx = tid; idx < LATENT * NPAD; idx += THREADS) {
        int k = idx / NPAD, c = idx - k * NPAD;
        sm[OFF_WCH + idx] = (c < NTRI) ? W_ch[k * NTRI + c] : 0.f;
    }
    for (int idx = tid; idx < LATENT * LATENT; idx += THREADS) sm[OFF_WMU + idx] = W_mu[idx];
    for (int idx = tid; idx < NPAD; idx += THREADS) sm[OFF_BCH + idx] = (idx < NTRI) ? b_ch[idx] : 0.f;
    __syncthreads();

    const int warp = tid >> 5, lane = tid & 31;
    float* xw = sm + OFF_WBUF + warp * WBUF_FLOATS;   // x quarter stage / two L buffers
    const float* wrow = sm + OFF_WENC + lane * WENC_PAD;
    const float bj = sm[OFF_BENC + lane];
    const float bm = sm[OFF_BMU + lane];

    // cov half-split lane mapping (round-10 proven)
    const int ch   = lane & 15;                 // base column (0..15)
    const int ch2  = ch + 16;                   // high column
    float* Lbh = xw + (lane >> 4) * LOFF_B;     // own-half L buffer (A or B)
    const int triC  = (ch  * (ch  + 1)) >> 1;
    const int triC2 = (ch2 * (ch2 + 1)) >> 1;

    for (int tile = blockIdx.x; tile < NTILES; tile += gridDim.x) {
        const int rbase = tile * TILE_ROWS + warp * RPW;

        // ---- enc GEMM: 8 rows, four quarter-K passes ----
        float h[RPW];
        #pragma unroll
        for (int r = 0; r < RPW; r++) h[r] = 0.f;

        #pragma unroll
        for (int q = 0; q < 4; q++) {
            // stage x[8][128] (coalesced float4: one per row)
            #pragma unroll
            for (int r = 0; r < RPW; r++) {
                float4 v = *(const float4*)(x + (size_t)(rbase + r) * IN_DIM + q * 128 + lane * 4);
                *(float4*)(xw + r * XQ + lane * 4) = v;
            }
            __syncwarp();
            const float* wq = wrow + q * 128;
            #pragma unroll 4
            for (int k = 0; k < 128; k += 4) {
                float4 wv = *(const float4*)(wq + k);
                #pragma unroll
                for (int r = 0; r < RPW; r++) {
                    float4 a = *(const float4*)(xw + r * XQ + k);   // uniform broadcast
                    h[r] = fmaf(a.x, wv.x, h[r]);
                    h[r] = fmaf(a.y, wv.y, h[r]);
                    h[r] = fmaf(a.z, wv.z, h[r]);
                    h[r] = fmaf(a.w, wv.w, h[r]);
                }
            }
            __syncwarp();   // reads of this quarter done before restage / L reuse
        }
        #pragma unroll
        for (int r = 0; r < RPW; r++) {
            h[r] = lrelu(h[r] + bj);
            out[(size_t)(rbase + r) * 32 + lane] = h[r];
        }

        // ---- two row-groups of 4: mu/ch + cov (round-10 proven) ----
        #pragma unroll 1
        for (int g = 0; g < 2; g++) {
            float h0 = h[4 * g + 0], h1 = h[4 * g + 1], h2 = h[4 * g + 2], h3 = h[4 * g + 3];
            const int gb = rbase + 4 * g;

            // mu + ch GEMMs (scalar)
            float amu0 = 0.f, amu1 = 0.f, amu2 = 0.f, amu3 = 0.f;
            float ac[4][17];
            #pragma unroll
            for (int r = 0; r < 4; r++)
                #pragma unroll
                for (int c = 0; c < 17; c++) ac[r][c] = 0.f;

            #pragma unroll 2
            for (int k = 0; k < LATENT; k++) {
                float hv0 = __shfl_sync(0xffffffffu, h0, k);
                float hv1 = __shfl_sync(0xffffffffu, h1, k);
                float hv2 = __shfl_sync(0xffffffffu, h2, k);
                float hv3 = __shfl_sync(0xffffffffu, h3, k);
                float wm = sm[OFF_WMU + k * 32 + lane];
                amu0 = fmaf(hv0, wm, amu0); amu1 = fmaf(hv1, wm, amu1);
                amu2 = fmaf(hv2, wm, amu2); amu3 = fmaf(hv3, wm, amu3);
                const float* wck = sm + OFF_WCH + k * NPAD + lane;
                #pragma unroll
                for (int c = 0; c < 17; c++) {
                    float wc = wck[c * 32];
                    ac[0][c] = fmaf(hv0, wc, ac[0][c]);
                    ac[1][c] = fmaf(hv1, wc, ac[1][c]);
                    ac[2][c] = fmaf(hv2, wc, ac[2][c]);
                    ac[3][c] = fmaf(hv3, wc, ac[3][c]);
                }
            }
            out[MU_OFF + (size_t)(gb + 0) * 32 + lane] = lrelu(amu0 + bm);
            out[MU_OFF + (size_t)(gb + 1) * 32 + lane] = lrelu(amu1 + bm);
            out[MU_OFF + (size_t)(gb + 2) * 32 + lane] = lrelu(amu2 + bm);
            out[MU_OFF + (size_t)(gb + 3) * 32 + lane] = lrelu(amu3 + bm);
            __syncwarp();   // xw reads (enc) / prior cov pass done

            // cov: 2 batch rows per pass via half-split broadcasts
            float* LbA = xw;
            float* LbB = xw + LOFF_B;
            #pragma unroll
            for (int p = 0; p < 2; p++) {
                #pragma unroll
                for (int cc = 0; cc < 17; cc++) {
                    int e = cc * 32 + lane;
                    if (cc == 16 && e >= NTRI) continue;
                    float bc = sm[OFF_BCH + e];
                    LbA[e] = lrelu(ac[2 * p + 0][cc] + bc);
                    LbB[e] = lrelu(ac[2 * p + 1][cc] + bc);
                }
                __syncwarp();
                {
                    int dio = ((lane * (lane + 1)) >> 1) + lane;
                    float d = LbA[dio];
                    float sp = (d > 20.f) ? d : log1pf(expf(d));
                    LbA[dio] = fminf(fmaxf(sp, 0.001f), 100.f) + 0.01f;
                    d = LbB[dio];
                    sp = (d > 20.f) ? d : log1pf(expf(d));
                    LbB[dio] = fminf(fmaxf(sp, 0.001f), 100.f) + 0.01f;
                }
                __syncwarp();
                float Lk1[16], Lk2[32];
                #pragma unroll
                for (int j = 0; j < 16; j++) Lk1[j] = (j <= ch)  ? Lbh[triC  + j] : 0.f;
                #pragma unroll
                for (int j = 0; j < 32; j++) Lk2[j] = (j <= ch2) ? Lbh[triC2 + j] : 0.f;

                float* oc = out + COV_OFF + (size_t)(gb + 2 * p + (lane >> 4)) * 1024;
                #pragma unroll
                for (int i = 0; i < 32; i++) {
                    const float* Lr = Lbh + ((i * (i + 1)) >> 1);
                    float a1a = 0.f, a1b = 0.f, a2a = 0.f, a2b = 0.f;
                    #pragma unroll
                    for (int j = 0; j <= i; j++) {
                        float lv = Lr[j];           // half-split broadcast: 1 wf, 2 rows
                        if (j < 16) {
                            if (j & 1) a1b = fmaf(Lk1[j], lv, a1b);
                            else       a1a = fmaf(Lk1[j], lv, a1a);
                        }
                        if (j & 1) a2b = fmaf(Lk2[j], lv, a2b);
                        else       a2a = fmaf(Lk2[j], lv, a2a);
                    }
                    float cv1 = a1a + a1b;
                    float cv2 = a2a + a2b;
                    if (i == ch)  cv1 += 0.01f;
                    if (i == ch2) cv2 += 0.01f;
                    oc[i * 32 + ch]  = cv1;
                    oc[i * 32 + ch2] = cv2;
                }
                __syncwarp();   // cov reads done before next scatter / next stage
            }
        }
    }
}

extern "C" void kernel_launch(void* const* d_in, const int* in_sizes, int n_in,
                              void* d_out, int out_size)
{
    (void)in_sizes; (void)n_in; (void)out_size;
    const float* x        = (const float*)d_in[0];
    const float* W_enc    = (const float*)d_in[1];
    const float* b_enc    = (const float*)d_in[2];
    const float* bn_gamma = (const float*)d_in[3];
    const float* bn_beta  = (const float*)d_in[4];
    const float* bn_mean  = (const float*)d_in[5];
    const float* bn_var   = (const float*)d_in[6];
    const float* W_mu     = (const float*)d_in[7];
    const float* b_mu     = (const float*)d_in[8];
    const float* W_ch     = (const float*)d_in[9];
    const float* b_ch     = (const float*)d_in[10];
    float* out = (float*)d_out;

    cudaFuncSetAttribute(pm_kernel, cudaFuncAttributeMaxDynamicSharedMemorySize,
                         SMEM_FLOATS * (int)sizeof(float));
    pm_kernel<<<GRID, THREADS, SMEM_FLOATS * sizeof(float)>>>(
        x, W_enc, b_enc, bn_gamma, bn_beta, bn_mean, bn_var,
        W_mu, b_mu, W_ch, b_ch, out);
}

// round 12
// speedup vs baseline: 1.0669x; 1.0669x over previous
#include <cuda_runtime.h>
#include <math.h>
#include <stdint.h>

#define BATCH   65536
#define IN_DIM  512
#define LATENT  32
#define NTRI    528
#define NPAD    544            // W_ch padded row (floats)
#define WENC_PAD 524           // conflict-free float4 weight rows
#define THREADS 512
#define WARPS   16
#define RPW     4
#define TILE_ROWS (WARPS*RPW)  // 64
#define NTILES  (BATCH/TILE_ROWS) // 1024
#define GRID    152

#define XH      272            // per-row stride (floats) of half-K x stage
#define LOFF_B  560            // cov buffer-B offset (bank set differs by 16 from A)
#define WBUF_FLOATS 1088       // per-warp buffer: 4x272 x-halves OR two packed-tri L rows

// ---- smem layout (floats) ----
#define OFF_WENC 0
#define SZ_WENC  (LATENT*WENC_PAD)              // 16768
#define OFF_WCH  (OFF_WENC + SZ_WENC)           // 16768 (col-pair interleaved, 544/row)
#define SZ_WCH   (LATENT*NPAD)                  // 17408
#define OFF_WMU  (OFF_WCH + SZ_WCH)             // 34176
#define OFF_BENC (OFF_WMU + LATENT*LATENT)      // 35200
#define OFF_BMU  (OFF_BENC + 32)                // 35232
#define OFF_BCH  (OFF_BMU + 32)                 // 35264 (544)
#define OFF_S    (OFF_BCH + NPAD)               // 35808
#define OFF_WBUF (OFF_S + 32)                   // 35840 (16B aligned)
#define SMEM_FLOATS (OFF_WBUF + WARPS*WBUF_FLOATS) // 53248 floats = 212992 B

#define MU_OFF  ((size_t)BATCH*LATENT)
#define COV_OFF ((size_t)BATCH*LATENT*2)

typedef unsigned long long ull;

__device__ __forceinline__ float lrelu(float v) { return v >= 0.f ? v : 0.01f * v; }
__device__ __forceinline__ ull pk2(float lo, float hi) {
    ull r; asm("mov.b64 %0, {%1,%2};" : "=l"(r) : "f"(lo), "f"(hi)); return r;
}
__device__ __forceinline__ float lo2(ull v) {
    float f; asm("{ .reg .f32 h; mov.b64 {%0, h}, %1; }" : "=f"(f) : "l"(v)); return f;
}
__device__ __forceinline__ float hi2(ull v) {
    float f; asm("{ .reg .f32 l; mov.b64 {l, %0}, %1; }" : "=f"(f) : "l"(v)); return f;
}
__device__ __forceinline__ ull fma2(ull a, ull b, ull c) {
    ull d; asm("fma.rn.f32x2 %0, %1, %2, %3;" : "=l"(d) : "l"(a), "l"(b), "l"(c)); return d;
}

__global__ void __launch_bounds__(THREADS)
pm_kernel(const float* __restrict__ x,       const float* __restrict__ W_enc,
          const float* __restrict__ b_enc,   const float* __restrict__ bn_gamma,
          const float* __restrict__ bn_beta, const float* __restrict__ bn_mean,
          const float* __restrict__ bn_var,  const float* __restrict__ W_mu,
          const float* __restrict__ b_mu,    const float* __restrict__ W_ch,
          const float* __restrict__ b_ch,    float* __restrict__ out)
{
    extern __shared__ float sm[];
    const int tid = threadIdx.x;

    // ---- stage + fold weights into smem ----
    if (tid < 32) {
        float s = bn_gamma[tid] * rsqrtf(bn_var[tid] + 1e-5f);
        sm[OFF_S + tid]    = s;
        sm[OFF_BENC + tid] = (b_enc[tid] - bn_mean[tid]) * s + bn_beta[tid];
        sm[OFF_BMU + tid]  = b_mu[tid];
    }
    __syncthreads();
    for (int idx = tid; idx < IN_DIM * LATENT; idx += THREADS) {
        int k = idx >> 5, j = idx & 31;
        sm[OFF_WENC + j * WENC_PAD + k] = W_enc[idx] * sm[OFF_S + j];  // transposed + BN fold
    }
    // W_ch col-pair interleave (round-4 proven): word w in row k:
    //   w < 512: cp=w>>6, ln=(w&63)>>1, s=w&1 -> col (2cp+s)*32+ln ; w>=512: col w (512..527, rest 0)
    for (int idx = tid; idx < LATENT * NPAD; idx += THREADS) {
        int k = idx / NPAD, w = idx - k * NPAD;
        float v;
        if (w < 512) {
            int cp = w >> 6, ln = (w & 63) >> 1, s = w & 1;
            v = W_ch[k * NTRI + (2 * cp + s) * 32 + ln];
        } else {
            v = (w < NTRI) ? W_ch[k * NTRI + w] : 0.f;
        }
        sm[OFF_WCH + idx] = v;
    }
    for (int idx = tid; idx < LATENT * LATENT; idx += THREADS) sm[OFF_WMU + idx] = W_mu[idx];
    for (int idx = tid; idx < NPAD; idx += THREADS) sm[OFF_BCH + idx] = (idx < NTRI) ? b_ch[idx] : 0.f;
    __syncthreads();

    const int warp = tid >> 5, lane = tid & 31;
    float* xw = sm + OFF_WBUF + warp * WBUF_FLOATS;   // x half stage / two L buffers
    const float* wrow = sm + OFF_WENC + lane * WENC_PAD;
    const float bj = sm[OFF_BENC + lane];
    const float bm = sm[OFF_BMU + lane];

    // cov half-split lane mapping (round-10 proven)
    const int ch   = lane & 15;
    const int ch2  = ch + 16;
    float* Lbh = xw + (lane >> 4) * LOFF_B;
    const int triC  = (ch  * (ch  + 1)) >> 1;
    const int triC2 = (ch2 * (ch2 + 1)) >> 1;

    for (int tile = blockIdx.x; tile < NTILES; tile += gridDim.x) {
        const int rbase = tile * TILE_ROWS + warp * RPW;

        // ---- enc GEMM in two half-K passes, second half prefetched ----
        float h0 = 0.f, h1 = 0.f, h2 = 0.f, h3 = 0.f;
        float4 pv[8];
        #pragma unroll
        for (int r = 0; r < RPW; r++)
            #pragma unroll
            for (int c = 0; c < 2; c++)
                pv[r * 2 + c] = *(const float4*)(x + (size_t)(rbase + r) * IN_DIM + c * 128 + lane * 4);

        #pragma unroll
        for (int half = 0; half < 2; half++) {
            #pragma unroll
            for (int r = 0; r < RPW; r++)
                #pragma unroll
                for (int c = 0; c < 2; c++)
                    *(float4*)(xw + r * XH + c * 128 + lane * 4) = pv[r * 2 + c];
            __syncwarp();
            if (half == 0) {            // prefetch half 1 while computing half 0
                #pragma unroll
                for (int r = 0; r < RPW; r++)
                    #pragma unroll
                    for (int c = 0; c < 2; c++)
                        pv[r * 2 + c] = *(const float4*)(x + (size_t)(rbase + r) * IN_DIM + 256 + c * 128 + lane * 4);
            }
            const float* wh = wrow + half * 256;
            #pragma unroll 4
            for (int k = 0; k < 256; k += 4) {
                float4 wv = *(const float4*)(wh + k);
                float4 a0 = *(const float4*)(xw + 0 * XH + k);
                float4 a1 = *(const float4*)(xw + 1 * XH + k);
                float4 a2 = *(const float4*)(xw + 2 * XH + k);
                float4 a3 = *(const float4*)(xw + 3 * XH + k);
                h0 = fmaf(a0.x, wv.x, h0); h0 = fmaf(a0.y, wv.y, h0); h0 = fmaf(a0.z, wv.z, h0); h0 = fmaf(a0.w, wv.w, h0);
                h1 = fmaf(a1.x, wv.x, h1); h1 = fmaf(a1.y, wv.y, h1); h1 = fmaf(a1.z, wv.z, h1); h1 = fmaf(a1.w, wv.w, h1);
                h2 = fmaf(a2.x, wv.x, h2); h2 = fmaf(a2.y, wv.y, h2); h2 = fmaf(a2.z, wv.z, h2); h2 = fmaf(a2.w, wv.w, h2);
                h3 = fmaf(a3.x, wv.x, h3); h3 = fmaf(a3.y, wv.y, h3); h3 = fmaf(a3.z, wv.z, h3); h3 = fmaf(a3.w, wv.w, h3);
            }
            __syncwarp();
        }
        h0 = lrelu(h0 + bj); h1 = lrelu(h1 + bj); h2 = lrelu(h2 + bj); h3 = lrelu(h3 + bj);
        out[(size_t)(rbase + 0) * 32 + lane] = h0;
        out[(size_t)(rbase + 1) * 32 + lane] = h1;
        out[(size_t)(rbase + 2) * 32 + lane] = h2;
        out[(size_t)(rbase + 3) * 32 + lane] = h3;

        // ---- mu + ch GEMMs (f32x2, col-pair weights — round-4 proven) ----
        ull acp[RPW][8];
        float ac16[RPW];
        ull amu01 = 0ull, amu23 = 0ull;
        #pragma unroll
        for (int r = 0; r < RPW; r++) {
            ac16[r] = 0.f;
            #pragma unroll
            for (int cp = 0; cp < 8; cp++) acp[r][cp] = 0ull;
        }
        #pragma unroll 2
        for (int k = 0; k < LATENT; k++) {
            float hv0 = __shfl_sync(0xffffffffu, h0, k);
            float hv1 = __shfl_sync(0xffffffffu, h1, k);
            float hv2 = __shfl_sync(0xffffffffu, h2, k);
            float hv3 = __shfl_sync(0xffffffffu, h3, k);
            float wm = sm[OFF_WMU + k * 32 + lane];
            ull wmd  = pk2(wm, wm);
            amu01 = fma2(pk2(hv0, hv1), wmd, amu01);
            amu23 = fma2(pk2(hv2, hv3), wmd, amu23);
            ull hd0 = pk2(hv0, hv0), hd1 = pk2(hv1, hv1), hd2 = pk2(hv2, hv2), hd3 = pk2(hv3, hv3);
            const ull* w2 = (const ull*)(sm + OFF_WCH + k * NPAD) + lane;
            #pragma unroll
            for (int cp = 0; cp < 8; cp++) {
                ull w = w2[cp * 32];
                acp[0][cp] = fma2(hd0, w, acp[0][cp]);
                acp[1][cp] = fma2(hd1, w, acp[1][cp]);
                acp[2][cp] = fma2(hd2, w, acp[2][cp]);
                acp[3][cp] = fma2(hd3, w, acp[3][cp]);
            }
            float wc16 = sm[OFF_WCH + k * NPAD + 512 + lane];
            ac16[0] = fmaf(hv0, wc16, ac16[0]);
            ac16[1] = fmaf(hv1, wc16, ac16[1]);
            ac16[2] = fmaf(hv2, wc16, ac16[2]);
            ac16[3] = fmaf(hv3, wc16, ac16[3]);
        }
        out[MU_OFF + (size_t)(rbase + 0) * 32 + lane] = lrelu(lo2(amu01) + bm);
        out[MU_OFF + (size_t)(rbase + 1) * 32 + lane] = lrelu(hi2(amu01) + bm);
        out[MU_OFF + (size_t)(rbase + 2) * 32 + lane] = lrelu(lo2(amu23) + bm);
        out[MU_OFF + (size_t)(rbase + 3) * 32 + lane] = lrelu(hi2(amu23) + bm);
        __syncwarp();   // enc reads of xw done

        // ---- cov: 2 batch rows per pass via half-split broadcasts (round-10 proven) ----
        float* LbA = xw;
        float* LbB = xw + LOFF_B;
        #pragma unroll
        for (int p = 0; p < 2; p++) {
            #pragma unroll
            for (int cc = 0; cc < 17; cc++) {
                int e = cc * 32 + lane;
                if (cc == 16 && e >= NTRI) continue;
                float bc = sm[OFF_BCH + e];
                float v0, v1;
                if (cc < 16) {
                    ull q0 = acp[2 * p + 0][cc >> 1], q1 = acp[2 * p + 1][cc >> 1];
                    if (cc & 1) { v0 = hi2(q0); v1 = hi2(q1); }
                    else        { v0 = lo2(q0); v1 = lo2(q1); }
                } else { v0 = ac16[2 * p]; v1 = ac16[2 * p + 1]; }
                LbA[e] = lrelu(v0 + bc);
                LbB[e] = lrelu(v1 + bc);
            }
            __syncwarp();
            {
                int dio = ((lane * (lane + 1)) >> 1) + lane;
                float d = LbA[dio];
                float sp = (d > 20.f) ? d : log1pf(expf(d));
                LbA[dio] = fminf(fmaxf(sp, 0.001f), 100.f) + 0.01f;
                d = LbB[dio];
                sp = (d > 20.f) ? d : log1pf(expf(d));
                LbB[dio] = fminf(fmaxf(sp, 0.001f), 100.f) + 0.01f;
            }
            __syncwarp();
            float Lk1[16], Lk2[32];
            #pragma unroll
            for (int j = 0; j < 16; j++) Lk1[j] = (j <= ch)  ? Lbh[triC  + j] : 0.f;
            #pragma unroll
            for (int j = 0; j < 32; j++) Lk2[j] = (j <= ch2) ? Lbh[triC2 + j] : 0.f;

            float* oc = out + COV_OFF + (size_t)(rbase + 2 * p + (lane >> 4)) * 1024;
            #pragma unroll
            for (int i = 0; i < 32; i++) {
                const float* Lr = Lbh + ((i * (i + 1)) >> 1);
                float a1a = 0.f, a1b = 0.f, a2a = 0.f, a2b = 0.f;
                #pragma unroll
                for (int j = 0; j <= i; j++) {
                    float lv = Lr[j];
                    if (j < 16) {
                        if (j & 1) a1b = fmaf(Lk1[j], lv, a1b);
                        else       a1a = fmaf(Lk1[j], lv, a1a);
                    }
                    if (j & 1) a2b = fmaf(Lk2[j], lv, a2b);
                    else       a2a = fmaf(Lk2[j], lv, a2a);
                }
                float cv1 = a1a + a1b;
                float cv2 = a2a + a2b;
                if (i == ch)  cv1 += 0.01f;
                if (i == ch2) cv2 += 0.01f;
                oc[i * 32 + ch]  = cv1;
                oc[i * 32 + ch2] = cv2;
            }
            __syncwarp();
        }
    }
}

extern "C" void kernel_launch(void* const* d_in, const int* in_sizes, int n_in,
                              void* d_out, int out_size)
{
    (void)in_sizes; (void)n_in; (void)out_size;
    const float* x        = (const float*)d_in[0];
    const float* W_enc    = (const float*)d_in[1];
    const float* b_enc    = (const float*)d_in[2];
    const float* bn_gamma = (const float*)d_in[3];
    const float* bn_beta  = (const float*)d_in[4];
    const float* bn_mean  = (const float*)d_in[5];
    const float* bn_var   = (const float*)d_in[6];
    const float* W_mu     = (const float*)d_in[7];
    const float* b_mu     = (const float*)d_in[8];
    const float* W_ch     = (const float*)d_in[9];
    const float* b_ch     = (const float*)d_in[10];
    float* out = (float*)d_out;

    cudaFuncSetAttribute(pm_kernel, cudaFuncAttributeMaxDynamicSharedMemorySize,
                         SMEM_FLOATS * (int)sizeof(float));
    pm_kernel<<<GRID, THREADS, SMEM_FLOATS * sizeof(float)>>>(
        x, W_enc, b_enc, bn_gamma, bn_beta, bn_mean, bn_var,
        W_mu, b_mu, W_ch, b_ch, out);
}